// round 1
// baseline (speedup 1.0000x reference)
#include <cuda_runtime.h>
#include <math.h>

#define Bn 512
#define Hn 1024
#define Sn 1024
#define Dn 128
#define Kn 32

// Output layout: [read (B*D)] [new_memory (B*S*D)] [weights (B*S)]
#define READ_OFF 0
#define MEM_OFF  (Bn*Dn)
#define W_OFF    (Bn*Dn + (size_t)Bn*Sn*Dn)

// Scratch (no allocation allowed -> device globals)
__device__ float g_query[Bn*Dn];
__device__ float g_value[Bn*Dn];
__device__ float g_logits[Bn*Sn];
__device__ float g_gate[Bn];

// ---------------------------------------------------------------------------
// K1: query = latent @ Wq + bq ; value = latent @ Wv + bv
// Block handles 8 batches; 256 threads = (d in 0..127) x (h-half in 0..1).
// gridDim = (B/8, 2) ; blockIdx.y selects which weight matrix.
// ---------------------------------------------------------------------------
__global__ __launch_bounds__(256, 2)
void qv_kernel(const float* __restrict__ latent,
               const float* __restrict__ Wq, const float* __restrict__ bq,
               const float* __restrict__ Wv, const float* __restrict__ bv)
{
    __shared__ float lat[8 * Hn];        // 32 KB
    __shared__ float part[8][Dn];        // 4 KB partials from h-half 1

    const int b0 = blockIdx.x * 8;
    const float* W    = blockIdx.y ? Wv : Wq;
    const float* bias = blockIdx.y ? bv : bq;
    float*       out  = blockIdx.y ? g_value : g_query;

    const int tid = threadIdx.x;

    // load 8 latent rows (8192 floats) coalesced as float4
    {
        const float4* src = (const float4*)(latent + (size_t)b0 * Hn);
        float4* dst = (float4*)lat;
        #pragma unroll
        for (int i = 0; i < 8; i++) dst[tid + i * 256] = src[tid + i * 256];
    }
    __syncthreads();

    const int d    = tid & 127;
    const int half = tid >> 7;
    const int hbase = half * 512;

    float acc[8];
    #pragma unroll
    for (int j = 0; j < 8; j++) acc[j] = 0.f;

    const float* Wp = W + (size_t)hbase * Dn + d;
    #pragma unroll 2
    for (int h = 0; h < 512; h++) {
        float w = Wp[(size_t)h * Dn];
        #pragma unroll
        for (int j = 0; j < 8; j++)
            acc[j] += lat[j * Hn + hbase + h] * w;
    }

    if (half == 1) {
        #pragma unroll
        for (int j = 0; j < 8; j++) part[j][d] = acc[j];
    }
    __syncthreads();
    if (half == 0) {
        float bb = bias[d];
        #pragma unroll
        for (int j = 0; j < 8; j++)
            out[(size_t)(b0 + j) * Dn + d] = acc[j] + part[j][d] + bb;
    }
}

// ---------------------------------------------------------------------------
// K2: logits[b,s] = dot(query[b], memory_key[s])   (D = 128 contraction)
// 32x32 output tile per block, smem float4 tiles padded to 33 f4/row.
// Warp w handles 4 batches, lane = s within tile (conflict-free LDS).
// gridDim = (B/32, S/32) = (16, 32), 256 threads.
// ---------------------------------------------------------------------------
__global__ __launch_bounds__(256, 4)
void logits_kernel(const float* __restrict__ key)
{
    __shared__ float4 qs[32 * 33];   // 16.9 KB
    __shared__ float4 ks[32 * 33];   // 16.9 KB

    const int b0 = blockIdx.x * 32;
    const int s0 = blockIdx.y * 32;
    const int tid = threadIdx.x;

    #pragma unroll
    for (int i = tid; i < 32 * 32; i += 256) {
        int r = i >> 5, c = i & 31;
        qs[r * 33 + c] = ((const float4*)(g_query + (size_t)(b0 + r) * Dn))[c];
        ks[r * 33 + c] = ((const float4*)(key     + (size_t)(s0 + r) * Dn))[c];
    }
    __syncthreads();

    const int lane = tid & 31;       // s index in tile
    const int br   = (tid >> 5) * 4; // first of 4 batches for this warp

    float a0 = 0.f, a1 = 0.f, a2 = 0.f, a3 = 0.f;
    #pragma unroll 8
    for (int k = 0; k < 32; k++) {
        float4 kv = ks[lane * 33 + k];
        float4 q;
        q = qs[(br + 0) * 33 + k]; a0 += q.x*kv.x + q.y*kv.y + q.z*kv.z + q.w*kv.w;
        q = qs[(br + 1) * 33 + k]; a1 += q.x*kv.x + q.y*kv.y + q.z*kv.z + q.w*kv.w;
        q = qs[(br + 2) * 33 + k]; a2 += q.x*kv.x + q.y*kv.y + q.z*kv.z + q.w*kv.w;
        q = qs[(br + 3) * 33 + k]; a3 += q.x*kv.x + q.y*kv.y + q.z*kv.z + q.w*kv.w;
    }
    g_logits[(size_t)(b0 + br + 0) * Sn + s0 + lane] = a0;
    g_logits[(size_t)(b0 + br + 1) * Sn + s0 + lane] = a1;
    g_logits[(size_t)(b0 + br + 2) * Sn + s0 + lane] = a2;
    g_logits[(size_t)(b0 + br + 3) * Sn + s0 + lane] = a3;
}

// ---------------------------------------------------------------------------
// K3: per-batch block (512 blocks, 256 threads):
//   top-32 of logits, softmax over the 32, write weights row (zeros+scatter),
//   read = sum_k w_k * memory[b, idx_k, :], then gate scalar math -> g_gate.
// ---------------------------------------------------------------------------
__global__ __launch_bounds__(256, 4)
void batch_kernel(const float* __restrict__ latent,
                  const float* __restrict__ memory,
                  const float* __restrict__ wg, const float* __restrict__ bg,
                  const float* __restrict__ wd, const float* __restrict__ bd,
                  const float* __restrict__ wp, const float* __restrict__ bp,
                  float* __restrict__ out)
{
    __shared__ float sl[Sn];       // logits row
    __shared__ int   ti[Kn];
    __shared__ float tw[Kn];
    __shared__ float rd[Dn];
    __shared__ float r3[24];

    const int b   = blockIdx.x;
    const int tid = threadIdx.x;

    for (int i = tid; i < Sn; i += 256) sl[i] = g_logits[(size_t)b * Sn + i];
    __syncthreads();

    // --- iterative top-32 by warp 0 ---
    if (tid < 32) {
        const int lane = tid;
        for (int it = 0; it < Kn; it++) {
            float bv = -1e30f; int bi = 0;
            #pragma unroll
            for (int j = 0; j < 32; j++) {
                float v = sl[lane + 32 * j];
                if (v > bv) { bv = v; bi = lane + 32 * j; }
            }
            #pragma unroll
            for (int o = 16; o; o >>= 1) {
                float ov = __shfl_xor_sync(0xffffffffu, bv, o);
                int   oi = __shfl_xor_sync(0xffffffffu, bi, o);
                if (ov > bv || (ov == bv && oi < bi)) { bv = ov; bi = oi; }
            }
            if ((bi & 31) == lane) sl[bi] = -1e30f;   // exactly one lane
            if (lane == 0) { ti[it] = bi; tw[it] = bv; }
            __syncwarp();
        }
        // softmax over the 32 kept logits (tw[0] is the global max)
        float m = tw[0];
        float e = __expf(tw[lane] - m);
        float s = e;
        #pragma unroll
        for (int o = 16; o; o >>= 1) s += __shfl_xor_sync(0xffffffffu, s, o);
        tw[lane] = e / s;
        __syncwarp();
    }
    __syncthreads();

    // --- weights row: zeros then scatter ---
    float* wout = out + W_OFF + (size_t)b * Sn;
    for (int i = tid; i < Sn; i += 256) wout[i] = 0.f;
    __syncthreads();
    if (tid < Kn) wout[ti[tid]] = tw[tid];

    // --- read gather: 128 threads, one per d ---
    if (tid < Dn) {
        float acc = 0.f;
        #pragma unroll 8
        for (int k = 0; k < Kn; k++)
            acc += tw[k] * memory[((size_t)b * Sn + ti[k]) * Dn + tid];
        out[READ_OFF + (size_t)b * Dn + tid] = acc;
        rd[tid] = acc;
    }
    __syncthreads();

    // --- gate dot products over gate_input = [latent(1024), read(128)] ---
    float pg = 0.f, pd = 0.f, pp = 0.f;
    const float* latb = latent + (size_t)b * Hn;
    for (int j = tid; j < Hn; j += 256) {
        float x = latb[j];
        pg += x * wg[j];
        pd += x * wd[j];
        pp += x * wp[j];
    }
    if (tid < Dn) {
        float x = rd[tid];
        pg += x * wg[Hn + tid];
        pd += x * wd[Hn + tid];
    }
    #pragma unroll
    for (int o = 16; o; o >>= 1) {
        pg += __shfl_xor_sync(0xffffffffu, pg, o);
        pd += __shfl_xor_sync(0xffffffffu, pd, o);
        pp += __shfl_xor_sync(0xffffffffu, pp, o);
    }
    const int wpid = tid >> 5, lane = tid & 31;
    if (lane == 0) { r3[wpid] = pg; r3[8 + wpid] = pd; r3[16 + wpid] = pp; }
    __syncthreads();
    if (tid == 0) {
        float G = 0.f, Dv = 0.f, P = 0.f;
        #pragma unroll
        for (int i = 0; i < 8; i++) { G += r3[i]; Dv += r3[8 + i]; P += r3[16 + i]; }
        float gate = 1.f / (1.f + __expf(-(G + bg[0])));
        float dmd  = tanhf(Dv + bd[0]);
        gate = gate * (0.75f + 0.5f * (dmd + 1.0f) * 0.5f);
        gate = fminf(fmaxf(gate, 0.f), 1.f);
        float ph = P + bp[0];
        gate *= 0.5f * (1.f + cosf(ph));
        g_gate[b] = gate;
    }
}

// ---------------------------------------------------------------------------
// K4: fused streaming copy + sparse blend (the HBM-bound pass).
// Each thread: 4 float4 per block-stride; one warp == one D-row, so the
// per-row weight load is a single broadcast (L1 hit).
// grid = B*S*D/4/1024 = 16384 blocks, 256 threads.
// ---------------------------------------------------------------------------
__global__ __launch_bounds__(256, 8)
void copy_update_kernel(const float4* __restrict__ mem4,
                        float* __restrict__ out)
{
    const float*  wts  = out + W_OFF;
    float4*       dst  = (float4*)(out + MEM_OFF);
    const float4* val4 = (const float4*)g_value;

    size_t base = (size_t)blockIdx.x * 1024 + threadIdx.x;
    #pragma unroll
    for (int j = 0; j < 4; j++) {
        size_t g = base + (size_t)j * 256;
        int row = (int)(g >> 5);          // b*S + s
        int bb  = row >> 10;
        float w = wts[row];               // warp-uniform broadcast
        float4 m = mem4[g];
        if (w != 0.f) {
            float gw = g_gate[bb] * w;
            float4 v = val4[((size_t)bb << 5) + (g & 31)];
            m.x = (1.f - gw) * m.x + gw * v.x;
            m.y = (1.f - gw) * m.y + gw * v.y;
            m.z = (1.f - gw) * m.z + gw * v.z;
            m.w = (1.f - gw) * m.w + gw * v.w;
        }
        dst[g] = m;
    }
}

// ---------------------------------------------------------------------------
extern "C" void kernel_launch(void* const* d_in, const int* in_sizes, int n_in,
                              void* d_out, int out_size)
{
    const float* latent    = (const float*)d_in[0];
    const float* memory    = (const float*)d_in[1];
    const float* rq_w      = (const float*)d_in[2];
    const float* rq_b      = (const float*)d_in[3];
    const float* mem_key   = (const float*)d_in[4];
    const float* wg_w      = (const float*)d_in[5];
    const float* wg_b      = (const float*)d_in[6];
    const float* wd_w      = (const float*)d_in[7];
    const float* wd_b      = (const float*)d_in[8];
    const float* wp_w      = (const float*)d_in[9];
    const float* wp_b      = (const float*)d_in[10];
    const float* wv_w      = (const float*)d_in[11];
    const float* wv_b      = (const float*)d_in[12];
    float* out = (float*)d_out;

    qv_kernel<<<dim3(Bn / 8, 2), 256>>>(latent, rq_w, rq_b, wv_w, wv_b);
    logits_kernel<<<dim3(Bn / 32, Sn / 32), 256>>>(mem_key);
    batch_kernel<<<Bn, 256>>>(latent, memory,
                              wg_w, wg_b, wd_w, wd_b, wp_w, wp_b, out);
    copy_update_kernel<<<(Bn * Sn * Dn / 4) / 1024, 256>>>((const float4*)memory, out);
}

// round 2
// speedup vs baseline: 1.7981x; 1.7981x over previous
#include <cuda_runtime.h>
#include <math.h>

#define Bn 512
#define Hn 1024
#define Sn 1024
#define Dn 128
#define Kn 32

// Output layout: [read (B*D)] [new_memory (B*S*D)] [weights (B*S)]
#define READ_OFF 0
#define MEM_OFF  (Bn*Dn)
#define W_OFF    (Bn*Dn + (size_t)Bn*Sn*Dn)

// Scratch (no allocation allowed -> device globals)
__device__ float4 g_query[Bn * (Dn/4)];   // [B][32] float4
__device__ float4 g_value[Bn * (Dn/4)];
__device__ float  g_logits[Bn * Sn];
__device__ float  g_gate[Bn];

// ---------------------------------------------------------------------------
// K1: query = latent @ Wq + bq ; value = latent @ Wv + bv
// 8 batches per block, 256 threads. Thread: dq = tid&31 (d-quad),
// hs = tid>>5 (h-slice of 128). acc[8 batches][4 d] = 32 fp32 regs.
// Per 4-h chunk: 4 LDG.128 (W, coalesced) + 8 LDS.128 (latent, broadcast)
// + 128 FFMA. Cross-slice reduction through smem overlay.
// grid (B/8, 2); blockIdx.y selects Wq vs Wv.
// ---------------------------------------------------------------------------
__global__ __launch_bounds__(256, 2)
void qv_kernel(const float* __restrict__ latent,
               const float* __restrict__ Wq, const float* __restrict__ bq,
               const float* __restrict__ Wv, const float* __restrict__ bv)
{
    __shared__ float4 smem[8 * 256];   // 32 KB: latent tile, then reduction overlay

    const int b0 = blockIdx.x * 8;
    const float4* W4    = (const float4*)(blockIdx.y ? Wv : Wq);
    const float4* bias4 = (const float4*)(blockIdx.y ? bv : bq);
    float4*       out4  = blockIdx.y ? g_value : g_query;

    const int tid = threadIdx.x;
    const int dq  = tid & 31;
    const int hs  = tid >> 5;

    // load 8 latent rows (8 x 1024 floats = 2048 float4), coalesced
    {
        const float4* src = (const float4*)(latent + (size_t)b0 * Hn);
        #pragma unroll
        for (int i = 0; i < 8; i++) smem[tid + i * 256] = src[tid + i * 256];
    }
    __syncthreads();

    float4 acc[8];
    #pragma unroll
    for (int j = 0; j < 8; j++) acc[j] = make_float4(0.f, 0.f, 0.f, 0.f);

    // h range for this slice: [hs*128, hs*128+128), in chunks of 4
    const int hbase = hs * 128;
    #pragma unroll 4
    for (int c = 0; c < 32; c++) {
        const int h0 = hbase + c * 4;
        float4 w0 = W4[(size_t)(h0 + 0) * 32 + dq];
        float4 w1 = W4[(size_t)(h0 + 1) * 32 + dq];
        float4 w2 = W4[(size_t)(h0 + 2) * 32 + dq];
        float4 w3 = W4[(size_t)(h0 + 3) * 32 + dq];
        #pragma unroll
        for (int j = 0; j < 8; j++) {
            float4 lf = smem[j * 256 + hs * 32 + c];   // broadcast
            acc[j].x += lf.x * w0.x + lf.y * w1.x + lf.z * w2.x + lf.w * w3.x;
            acc[j].y += lf.x * w0.y + lf.y * w1.y + lf.z * w2.y + lf.w * w3.y;
            acc[j].z += lf.x * w0.z + lf.y * w1.z + lf.z * w2.z + lf.w * w3.z;
            acc[j].w += lf.x * w0.w + lf.y * w1.w + lf.z * w2.w + lf.w * w3.w;
        }
    }
    __syncthreads();   // done reading latent tile; overlay reduction buffer

    // red[hs][j][dq] : 8*8*32 float4 = 32 KB (overlays smem)
    #pragma unroll
    for (int j = 0; j < 8; j++) smem[hs * 256 + j * 32 + dq] = acc[j];
    __syncthreads();

    // 256 threads = 8 j x 32 dq: sum over the 8 slices
    {
        const int j2  = tid >> 5;
        const int dq2 = tid & 31;
        float4 s = make_float4(0.f, 0.f, 0.f, 0.f);
        #pragma unroll
        for (int h = 0; h < 8; h++) {
            float4 v = smem[h * 256 + j2 * 32 + dq2];
            s.x += v.x; s.y += v.y; s.z += v.z; s.w += v.w;
        }
        float4 bb = bias4[dq2];
        s.x += bb.x; s.y += bb.y; s.z += bb.z; s.w += bb.w;
        out4[(size_t)(b0 + j2) * 32 + dq2] = s;
    }
}

// ---------------------------------------------------------------------------
// K2: logits[b,s] = dot(query[b], memory_key[s]), D=128 contraction.
// 64b x 64s tile per block, 256 threads, thread computes 4b x 4s
// (interleaved by 16 for conflict-free padded-row LDS).
// Dynamic smem: 2 x 64 x 33 float4 = 67.6 KB.
// grid (B/64, S/64) = (8, 16).
// ---------------------------------------------------------------------------
#define L_SMEM_BYTES (2 * 64 * 33 * (int)sizeof(float4))

__global__ __launch_bounds__(256, 1)
void logits_kernel(const float* __restrict__ key)
{
    extern __shared__ float4 dyn[];
    float4* qs = dyn;             // [64][33]
    float4* ks = dyn + 64 * 33;   // [64][33]

    const int b0 = blockIdx.x * 64;
    const int s0 = blockIdx.y * 64;
    const int tid = threadIdx.x;

    const float4* q4 = g_query;
    const float4* k4 = (const float4*)key;
    #pragma unroll
    for (int i = tid; i < 64 * 32; i += 256) {
        int r = i >> 5, c = i & 31;
        qs[r * 33 + c] = q4[(size_t)(b0 + r) * 32 + c];
        ks[r * 33 + c] = k4[(size_t)(s0 + r) * 32 + c];
    }
    __syncthreads();

    const int tx = tid & 15;   // s base lane
    const int ty = tid >> 4;   // b base lane (0..15)

    float acc[4][4];
    #pragma unroll
    for (int i = 0; i < 4; i++)
        #pragma unroll
        for (int j = 0; j < 4; j++) acc[i][j] = 0.f;

    #pragma unroll 8
    for (int c = 0; c < 32; c++) {
        float4 qv[4], kv[4];
        #pragma unroll
        for (int i = 0; i < 4; i++) qv[i] = qs[(ty + 16 * i) * 33 + c];
        #pragma unroll
        for (int j = 0; j < 4; j++) kv[j] = ks[(tx + 16 * j) * 33 + c];
        #pragma unroll
        for (int i = 0; i < 4; i++)
            #pragma unroll
            for (int j = 0; j < 4; j++)
                acc[i][j] += qv[i].x * kv[j].x + qv[i].y * kv[j].y
                           + qv[i].z * kv[j].z + qv[i].w * kv[j].w;
    }

    #pragma unroll
    for (int i = 0; i < 4; i++)
        #pragma unroll
        for (int j = 0; j < 4; j++)
            g_logits[(size_t)(b0 + ty + 16 * i) * Sn + s0 + tx + 16 * j] = acc[i][j];
}

// ---------------------------------------------------------------------------
// K3: per-batch block (512 blocks, 256 threads): top-32, softmax-32,
// weights row write, read gather, gate scalar math.
// ---------------------------------------------------------------------------
__global__ __launch_bounds__(256, 4)
void batch_kernel(const float* __restrict__ latent,
                  const float* __restrict__ memory,
                  const float* __restrict__ wg, const float* __restrict__ bg,
                  const float* __restrict__ wd, const float* __restrict__ bd,
                  const float* __restrict__ wp, const float* __restrict__ bp,
                  float* __restrict__ out)
{
    __shared__ float sl[Sn];
    __shared__ int   ti[Kn];
    __shared__ float tw[Kn];
    __shared__ float rd[Dn];
    __shared__ float r3[24];

    const int b   = blockIdx.x;
    const int tid = threadIdx.x;

    for (int i = tid; i < Sn; i += 256) sl[i] = g_logits[(size_t)b * Sn + i];
    __syncthreads();

    // iterative top-32 by warp 0 (smallest-index tiebreak, matches top_k)
    if (tid < 32) {
        const int lane = tid;
        for (int it = 0; it < Kn; it++) {
            float bv = -1e30f; int bi = 0;
            #pragma unroll
            for (int j = 0; j < 32; j++) {
                float v = sl[lane + 32 * j];
                if (v > bv) { bv = v; bi = lane + 32 * j; }
            }
            #pragma unroll
            for (int o = 16; o; o >>= 1) {
                float ov = __shfl_xor_sync(0xffffffffu, bv, o);
                int   oi = __shfl_xor_sync(0xffffffffu, bi, o);
                if (ov > bv || (ov == bv && oi < bi)) { bv = ov; bi = oi; }
            }
            if ((bi & 31) == lane) sl[bi] = -1e30f;
            if (lane == 0) { ti[it] = bi; tw[it] = bv; }
            __syncwarp();
        }
        float m = tw[0];
        float e = __expf(tw[lane] - m);
        float s = e;
        #pragma unroll
        for (int o = 16; o; o >>= 1) s += __shfl_xor_sync(0xffffffffu, s, o);
        tw[lane] = e / s;
        __syncwarp();
    }
    __syncthreads();

    // weights row: zeros then scatter
    float* wout = out + W_OFF + (size_t)b * Sn;
    for (int i = tid; i < Sn; i += 256) wout[i] = 0.f;
    __syncthreads();
    if (tid < Kn) wout[ti[tid]] = tw[tid];

    // read gather
    if (tid < Dn) {
        float acc = 0.f;
        #pragma unroll 8
        for (int k = 0; k < Kn; k++)
            acc += tw[k] * memory[((size_t)b * Sn + ti[k]) * Dn + tid];
        out[READ_OFF + (size_t)b * Dn + tid] = acc;
        rd[tid] = acc;
    }
    __syncthreads();

    // gate dot products over [latent(1024), read(128)]
    float pg = 0.f, pd = 0.f, pp = 0.f;
    const float* latb = latent + (size_t)b * Hn;
    for (int j = tid; j < Hn; j += 256) {
        float x = latb[j];
        pg += x * wg[j];
        pd += x * wd[j];
        pp += x * wp[j];
    }
    if (tid < Dn) {
        float x = rd[tid];
        pg += x * wg[Hn + tid];
        pd += x * wd[Hn + tid];
    }
    #pragma unroll
    for (int o = 16; o; o >>= 1) {
        pg += __shfl_xor_sync(0xffffffffu, pg, o);
        pd += __shfl_xor_sync(0xffffffffu, pd, o);
        pp += __shfl_xor_sync(0xffffffffu, pp, o);
    }
    const int wpid = tid >> 5, lane = tid & 31;
    if (lane == 0) { r3[wpid] = pg; r3[8 + wpid] = pd; r3[16 + wpid] = pp; }
    __syncthreads();
    if (tid == 0) {
        float G = 0.f, Dv = 0.f, P = 0.f;
        #pragma unroll
        for (int i = 0; i < 8; i++) { G += r3[i]; Dv += r3[8 + i]; P += r3[16 + i]; }
        float gate = 1.f / (1.f + __expf(-(G + bg[0])));
        float dmd  = tanhf(Dv + bd[0]);
        gate = gate * (0.75f + 0.5f * (dmd + 1.0f) * 0.5f);
        gate = fminf(fmaxf(gate, 0.f), 1.f);
        float ph = P + bp[0];
        gate *= 0.5f * (1.f + cosf(ph));
        g_gate[b] = gate;
    }
}

// ---------------------------------------------------------------------------
// K4: fused streaming copy + sparse blend (HBM-bound). Streaming hints on the
// 256 MB read/write; weights stay cacheable (warp-uniform broadcast).
// ---------------------------------------------------------------------------
__global__ __launch_bounds__(256, 8)
void copy_update_kernel(const float4* __restrict__ mem4,
                        float* __restrict__ out)
{
    const float*  wts  = out + W_OFF;
    float4*       dst  = (float4*)(out + MEM_OFF);
    const float4* val4 = g_value;

    size_t base = (size_t)blockIdx.x * 1024 + threadIdx.x;
    #pragma unroll
    for (int j = 0; j < 4; j++) {
        size_t g = base + (size_t)j * 256;
        int row = (int)(g >> 5);          // b*S + s
        int bb  = row >> 10;
        float w = __ldg(&wts[row]);       // warp-uniform broadcast
        float4 m = __ldcs(&mem4[g]);
        if (w != 0.f) {
            float gw = g_gate[bb] * w;
            float4 v = val4[((size_t)bb << 5) + (g & 31)];
            m.x = (1.f - gw) * m.x + gw * v.x;
            m.y = (1.f - gw) * m.y + gw * v.y;
            m.z = (1.f - gw) * m.z + gw * v.z;
            m.w = (1.f - gw) * m.w + gw * v.w;
        }
        __stcs(&dst[g], m);
    }
}

// ---------------------------------------------------------------------------
extern "C" void kernel_launch(void* const* d_in, const int* in_sizes, int n_in,
                              void* d_out, int out_size)
{
    const float* latent    = (const float*)d_in[0];
    const float* memory    = (const float*)d_in[1];
    const float* rq_w      = (const float*)d_in[2];
    const float* rq_b      = (const float*)d_in[3];
    const float* mem_key   = (const float*)d_in[4];
    const float* wg_w      = (const float*)d_in[5];
    const float* wg_b      = (const float*)d_in[6];
    const float* wd_w      = (const float*)d_in[7];
    const float* wd_b      = (const float*)d_in[8];
    const float* wp_w      = (const float*)d_in[9];
    const float* wp_b      = (const float*)d_in[10];
    const float* wv_w      = (const float*)d_in[11];
    const float* wv_b      = (const float*)d_in[12];
    float* out = (float*)d_out;

    cudaFuncSetAttribute(logits_kernel,
                         cudaFuncAttributeMaxDynamicSharedMemorySize, L_SMEM_BYTES);

    qv_kernel<<<dim3(Bn / 8, 2), 256>>>(latent, rq_w, rq_b, wv_w, wv_b);
    logits_kernel<<<dim3(Bn / 64, Sn / 64), 256, L_SMEM_BYTES>>>(mem_key);
    batch_kernel<<<Bn, 256>>>(latent, memory,
                              wg_w, wg_b, wd_w, wd_b, wp_w, wp_b, out);
    copy_update_kernel<<<(Bn * Sn * Dn / 4) / 1024, 256>>>((const float4*)memory, out);
}